// round 6
// baseline (speedup 1.0000x reference)
#include <cuda_runtime.h>
#include <cuda_bf16.h>

#define NS     4
#define NA     8192
#define NC     8
#define THR2   1.21f
#define GRID   32
#define CELLS  (GRID * GRID * GRID)       // 32768
#define SROW   (CELLS + 4)                // starts row stride, 16B-multiple
#define ORIGIN (-22.0f)
#define INV_H  (1.0f / 1.375f)            // cell size 1.375 >= 1.1 + margin

// Device-global scratch (allocation in kernel_launch is forbidden).
// g_counts / g_npc are zero-init at load; finalize re-zeroes after consuming.
__device__ int g_counts[NS * NC * NC];
__device__ int g_npc[NC];
__device__ __align__(16) int    g_cellCounts[NS][CELLS];
__device__ __align__(16) int    g_cellStarts[NS][SROW];
__device__ __align__(16) float4 g_pk[NS][NA];   // (x,y,z,q) cell-sorted
__device__ __align__(16) int    g_meta[NS][NA]; // chain<<16 | atom id

__device__ __forceinline__ int cellco(float v) {
    int c = __float2int_rd((v - ORIGIN) * INV_H);
    return min(GRID - 1, max(0, c));
}

// ---------------------------------------------------------------------------
// build: per-sample uniform grid (count -> scan -> scatter). One block/sample.
__global__ __launch_bounds__(1024, 1) void build_kernel(
    const float* __restrict__ coord,
    const int*   __restrict__ asym,
    const int*   __restrict__ a2t)
{
    __shared__ int s_scan[1024];
    __shared__ int s_h[NC];

    int s   = blockIdx.x;
    int tid = threadIdx.x;
    const float* C = coord + (size_t)s * NA * 3;

    // phase A: zero cell counts (32768 ints, int4-wide; row is 16B-aligned)
    int4* cc4 = (int4*)g_cellCounts[s];
    for (int k = tid; k < CELLS / 4; k += 1024)
        cc4[k] = make_int4(0, 0, 0, 0);
    if (tid < NC) s_h[tid] = 0;
    __syncthreads();

    // phase B: histogram; remember (cell, rank) per atom
    int cell[NA / 1024], rank[NA / 1024];
#pragma unroll
    for (int r = 0; r < NA / 1024; ++r) {
        int a = tid + r * 1024;
        float x = C[3 * a], y = C[3 * a + 1], z = C[3 * a + 2];
        cell[r] = cellco(x) + GRID * (cellco(y) + GRID * cellco(z));
        rank[r] = atomicAdd(&g_cellCounts[s][cell[r]], 1);
    }
    __syncthreads();

    // phase C: exclusive scan of cell counts (32 cells per thread)
    int base = tid * 32;
    const int4* mine = (const int4*)(g_cellCounts[s] + base);
    int4 v[8];
    int sum = 0;
#pragma unroll
    for (int k = 0; k < 8; ++k) {
        v[k] = mine[k];
        sum += v[k].x + v[k].y + v[k].z + v[k].w;
    }
    s_scan[tid] = sum;
    __syncthreads();
    for (int off = 1; off < 1024; off <<= 1) {   // Hillis-Steele inclusive
        int a = s_scan[tid];
        int b = (tid >= off) ? s_scan[tid - off] : 0;
        __syncthreads();
        s_scan[tid] = a + b;
        __syncthreads();
    }
    int run = (tid > 0) ? s_scan[tid - 1] : 0;
    int4* st4 = (int4*)(g_cellStarts[s] + base);   // base is 128B-aligned
#pragma unroll
    for (int k = 0; k < 8; ++k) {
        int4 o;
        o.x = run;           run += v[k].x;
        o.y = run;           run += v[k].y;
        o.z = run;           run += v[k].z;
        o.w = run;           run += v[k].w;
        st4[k] = o;
    }
    if (tid == 1023) g_cellStarts[s][CELLS] = run;   // == NA
    __syncthreads();

    // phase D: scatter packed atoms in cell order (+ npc histogram on s==0)
#pragma unroll
    for (int r = 0; r < NA / 1024; ++r) {
        int a = tid + r * 1024;
        float x = C[3 * a], y = C[3 * a + 1], z = C[3 * a + 2];
        float q = fmaf(x, x, fmaf(y, y, z * z));
        int ch = asym[a2t[a]];
        int pos = g_cellStarts[s][cell[r]] + rank[r];
        g_pk[s][pos]   = make_float4(x, y, z, q);
        g_meta[s][pos] = (ch << 16) | a;
        if (s == 0) atomicAdd(&s_h[ch], 1);
    }
    if (s == 0) {
        __syncthreads();
        if (tid < NC) atomicAdd(&g_npc[tid], s_h[tid]);
    }
}

// ---------------------------------------------------------------------------
// search: one thread per cell-sorted atom; scan 27-cell stencil as 9
// x-contiguous ranges. Same fp32 association as the accepted brute-force
// kernel: d = fma(-2z, zj, fma(-2y, yj, fma(-2x, xj, qj))) + (qi - thr^2).
__global__ __launch_bounds__(256, 8) void search_kernel() {
    __shared__ int scnt[NC * NC];

    int t   = blockIdx.x * 256 + threadIdx.x;   // 0 .. NS*NA-1
    int s   = t >> 13;
    int k   = t & (NA - 1);
    int tid = threadIdx.x;

    if (tid < NC * NC) scnt[tid] = 0;
    __syncthreads();

    float4 p = g_pk[s][k];
    int    m = g_meta[s][k];
    int    ci   = m >> 16;
    int    myid = m & 0xFFFF;

    float m2x = -2.0f * p.x, m2y = -2.0f * p.y, m2z = -2.0f * p.z;
    float K   = p.w - THR2;

    int cx = cellco(p.x), cy = cellco(p.y), cz = cellco(p.z);
    int x0 = max(cx - 1, 0), x1 = min(cx + 1, GRID - 1);
    int y0 = max(cy - 1, 0), y1 = min(cy + 1, GRID - 1);
    int z0 = max(cz - 1, 0), z1 = min(cz + 1, GRID - 1);

    const float4* pk = g_pk[s];
    const int*    mt = g_meta[s];
    const int*    st = g_cellStarts[s];
    int bucket = ci * NC;

    for (int zz = z0; zz <= z1; ++zz) {
        for (int yy = y0; yy <= y1; ++yy) {
            int row = GRID * (yy + GRID * zz);
            int lo = st[row + x0];
            int hi = st[row + x1 + 1];
            int j = lo;
            for (; j + 1 < hi; j += 2) {
                float4 a = pk[j];
                float4 b = pk[j + 1];
                int ma = mt[j];
                int mb = mt[j + 1];
                float da = fmaf(m2z, a.z, fmaf(m2y, a.y, fmaf(m2x, a.x, a.w))) + K;
                float db = fmaf(m2z, b.z, fmaf(m2y, b.y, fmaf(m2x, b.x, b.w))) + K;
                if (da < 0.0f && (ma & 0xFFFF) > myid && (ma >> 16) != ci)
                    atomicAdd(&scnt[bucket + (ma >> 16)], 1);
                if (db < 0.0f && (mb & 0xFFFF) > myid && (mb >> 16) != ci)
                    atomicAdd(&scnt[bucket + (mb >> 16)], 1);
            }
            if (j < hi) {
                float4 a = pk[j];
                int ma = mt[j];
                float da = fmaf(m2z, a.z, fmaf(m2y, a.y, fmaf(m2x, a.x, a.w))) + K;
                if (da < 0.0f && (ma & 0xFFFF) > myid && (ma >> 16) != ci)
                    atomicAdd(&scnt[bucket + (ma >> 16)], 1);
            }
        }
    }

    __syncthreads();
    if (tid < NC * NC) {
        int v = scnt[tid];
        if (v) atomicAdd(&g_counts[s * NC * NC + tid], v);
    }
}

// ---------------------------------------------------------------------------
// layout: [ has (S*C*C floats) | details (S*C*C*2 floats, (total, rel)) ]
__global__ void finalize_kernel(float* __restrict__ out) {
    int tid = threadIdx.x;          // 0..255 -> (s, a, b)
    int s = tid >> 6;
    int r = tid & 63;
    int a = r >> 3;
    int b = r & 7;

    int tot_i = 0;
    if (a != b)   // each unordered cross pair counted exactly once total
        tot_i = g_counts[s * NC * NC + a * NC + b] +
                g_counts[s * NC * NC + b * NC + a];
    float tot = (float)tot_i;
    float mn  = (float)min(g_npc[a], g_npc[b]);
    float rel = tot / mn;
    bool  has = (tot > 100.0f) || (rel > 0.5f);

    out[tid]                        = has ? 1.0f : 0.0f;
    out[NS * NC * NC + 2 * tid]     = tot;
    out[NS * NC * NC + 2 * tid + 1] = rel;

    __syncthreads();                // everyone done reading accumulators
    g_counts[tid] = 0;              // reset for next graph replay
    if (tid < NC) g_npc[tid] = 0;
}

// ---------------------------------------------------------------------------
extern "C" void kernel_launch(void* const* d_in, const int* in_sizes, int n_in,
                              void* d_out, int out_size) {
    const float* coord = (const float*)d_in[0];   // [S, N, 3] f32
    const int*   asym  = (const int*)  d_in[1];   // [N_TOKENS] i32
    const int*   a2t   = (const int*)  d_in[2];   // [N] i32
    float*       out   = (float*)d_out;

    build_kernel<<<NS, 1024>>>(coord, asym, a2t);
    search_kernel<<<(NS * NA) / 256, 256>>>();
    finalize_kernel<<<1, 256>>>(out);
}

// round 7
// speedup vs baseline: 1.2988x; 1.2988x over previous
#include <cuda_runtime.h>
#include <cuda_bf16.h>

#define NS     4
#define NA     8192
#define NC     8
#define THR2   1.21f
#define GRID   32
#define CELLS  (GRID * GRID * GRID)       // 32768
#define SROW   (CELLS + 4)                // padded row stride (16B multiple)
#define ORIGIN (-22.0f)
#define INV_H  (1.0f / 1.375f)            // cell 1.375 >= 1.1 clash radius

// Device-global scratch (allocation in kernel_launch is forbidden).
// Invariants across graph replays: g_counts, g_npc, g_cellCounts are zero on
// entry (zero-init at load; consumers re-zero after reading each replay).
__device__ int g_counts[NS * NC * NC];
__device__ int g_npc[NC];
__device__ __align__(16) int    g_cellCounts[NS][CELLS];
__device__ __align__(16) int    g_cellStarts[NS][SROW];
__device__ __align__(16) int    g_cursor[NS][SROW];
__device__ int    g_cellOf[NS * NA];
__device__ int    g_chain[NA];
__device__ __align__(16) float4 g_pk[NS][NA];   // (x,y,z,q) cell-sorted
__device__ int    g_meta[NS][NA];               // chain<<16 | atom id

__device__ __forceinline__ int cellco(float v) {
    int c = __float2int_rd((v - ORIGIN) * INV_H);
    return min(GRID - 1, max(0, c));
}

// ---------------------------------------------------------------------------
// 1) hist: one thread per (sample, atom). Counts per cell (no-return REDG),
//    caches cell id, builds chain map + per-chain histogram once.
__global__ __launch_bounds__(256) void hist_kernel(
    const float* __restrict__ coord,
    const int*   __restrict__ asym,
    const int*   __restrict__ a2t)
{
    int t = blockIdx.x * 256 + threadIdx.x;   // 0 .. NS*NA-1
    int s = t >> 13;
    float x = coord[3 * t], y = coord[3 * t + 1], z = coord[3 * t + 2];
    int cell = cellco(x) + GRID * (cellco(y) + GRID * cellco(z));
    g_cellOf[t] = cell;
    atomicAdd(&g_cellCounts[s][cell], 1);
    if (t < NA) {
        int ch = asym[a2t[t]];
        g_chain[t] = ch;
        atomicAdd(&g_npc[ch], 1);
    }
}

// ---------------------------------------------------------------------------
// 2) scan: one block per sample. Exclusive scan of cell counts -> starts and
//    a cursor copy for scatter; zeroes counts afterwards (replay invariant).
__global__ __launch_bounds__(1024, 1) void scan_kernel() {
    __shared__ int s_scan[1024];
    int s   = blockIdx.x;
    int tid = threadIdx.x;

    int base = tid * 32;
    const int4* mine = (const int4*)(g_cellCounts[s] + base);
    int4 v[8];
    int sum = 0;
#pragma unroll
    for (int k = 0; k < 8; ++k) {
        v[k] = mine[k];
        sum += v[k].x + v[k].y + v[k].z + v[k].w;
    }
    s_scan[tid] = sum;
    __syncthreads();
    for (int off = 1; off < 1024; off <<= 1) {   // Hillis-Steele inclusive
        int a = s_scan[tid];
        int b = (tid >= off) ? s_scan[tid - off] : 0;
        __syncthreads();
        s_scan[tid] = a + b;
        __syncthreads();
    }
    int run = (tid > 0) ? s_scan[tid - 1] : 0;
    int4* st4 = (int4*)(g_cellStarts[s] + base);
    int4* cu4 = (int4*)(g_cursor[s] + base);
    int4* cc4 = (int4*)(g_cellCounts[s] + base);
#pragma unroll
    for (int k = 0; k < 8; ++k) {
        int4 o;
        o.x = run;           run += v[k].x;
        o.y = run;           run += v[k].y;
        o.z = run;           run += v[k].z;
        o.w = run;           run += v[k].w;
        st4[k] = o;
        cu4[k] = o;
        cc4[k] = make_int4(0, 0, 0, 0);          // restore invariant
    }
    if (tid == 1023) g_cellStarts[s][CELLS] = run;   // == NA
}

// ---------------------------------------------------------------------------
// 3) scatter: one thread per (sample, atom); rank via cursor atomics.
__global__ __launch_bounds__(256) void scatter_kernel(
    const float* __restrict__ coord)
{
    int t = blockIdx.x * 256 + threadIdx.x;
    int s = t >> 13;
    int a = t & (NA - 1);
    float x = coord[3 * t], y = coord[3 * t + 1], z = coord[3 * t + 2];
    float q = fmaf(x, x, fmaf(y, y, z * z));
    int cell = g_cellOf[t];
    int pos  = atomicAdd(&g_cursor[s][cell], 1);
    g_pk[s][pos]   = make_float4(x, y, z, q);
    g_meta[s][pos] = (g_chain[a] << 16) | a;
}

// ---------------------------------------------------------------------------
// 4) search: one thread per (atom, z-plane of stencil); each scans <=3
//    x-contiguous row ranges. Pair predicate keeps the exact fp32 association
//    of the accepted brute-force kernel. Pair counted once (id_j > id_i).
__global__ __launch_bounds__(256, 8) void search_kernel() {
    __shared__ int scnt[NC * NC];
    int tid = threadIdx.x;
    if (tid < NC * NC) scnt[tid] = 0;
    __syncthreads();

    int b    = blockIdx.x;            // 0 .. 383
    int zoff = b >> 7;                // 0..2
    int t    = ((b & 127) << 8) | tid;
    int s    = t >> 13;
    int k    = t & (NA - 1);

    float4 p = g_pk[s][k];
    int    m = g_meta[s][k];
    int    ci   = m >> 16;
    int    myid = m & 0xFFFF;

    float m2x = -2.0f * p.x, m2y = -2.0f * p.y, m2z = -2.0f * p.z;
    float K   = p.w - THR2;

    int cx = cellco(p.x), cy = cellco(p.y);
    int zz = cellco(p.z) + zoff - 1;
    int x0 = max(cx - 1, 0), x1 = min(cx + 1, GRID - 1);
    int y0 = max(cy - 1, 0), y1 = min(cy + 1, GRID - 1);

    if (zz >= 0 && zz < GRID) {
        const float4* pk = g_pk[s];
        const int*    mt = g_meta[s];
        const int*    st = g_cellStarts[s];
        int bucket = ci * NC;

        for (int yy = y0; yy <= y1; ++yy) {
            int row = GRID * (yy + GRID * zz);
            int lo = st[row + x0];
            int hi = st[row + x1 + 1];
            int j = lo;
            for (; j + 1 < hi; j += 2) {
                float4 a = pk[j];
                float4 c = pk[j + 1];
                int ma = mt[j];
                int mb = mt[j + 1];
                float da = fmaf(m2z, a.z, fmaf(m2y, a.y, fmaf(m2x, a.x, a.w))) + K;
                float db = fmaf(m2z, c.z, fmaf(m2y, c.y, fmaf(m2x, c.x, c.w))) + K;
                if (da < 0.0f && (ma & 0xFFFF) > myid && (ma >> 16) != ci)
                    atomicAdd(&scnt[bucket + (ma >> 16)], 1);
                if (db < 0.0f && (mb & 0xFFFF) > myid && (mb >> 16) != ci)
                    atomicAdd(&scnt[bucket + (mb >> 16)], 1);
            }
            if (j < hi) {
                float4 a = pk[j];
                int ma = mt[j];
                float da = fmaf(m2z, a.z, fmaf(m2y, a.y, fmaf(m2x, a.x, a.w))) + K;
                if (da < 0.0f && (ma & 0xFFFF) > myid && (ma >> 16) != ci)
                    atomicAdd(&scnt[bucket + (ma >> 16)], 1);
            }
        }
    }

    __syncthreads();
    if (tid < NC * NC) {
        int v = scnt[tid];
        if (v) atomicAdd(&g_counts[s * NC * NC + tid], v);
    }
}

// ---------------------------------------------------------------------------
// 5) finalize: thresholds + output; resets replay accumulators.
// layout: [ has (S*C*C floats) | details (S*C*C*2 floats, (total, rel)) ]
__global__ void finalize_kernel(float* __restrict__ out) {
    int tid = threadIdx.x;          // 0..255 -> (s, a, b)
    int s = tid >> 6;
    int r = tid & 63;
    int a = r >> 3;
    int b = r & 7;

    int tot_i = 0;
    if (a != b)   // each unordered cross pair counted exactly once total
        tot_i = g_counts[s * NC * NC + a * NC + b] +
                g_counts[s * NC * NC + b * NC + a];
    float tot = (float)tot_i;
    float mn  = (float)min(g_npc[a], g_npc[b]);
    float rel = tot / mn;
    bool  has = (tot > 100.0f) || (rel > 0.5f);

    out[tid]                        = has ? 1.0f : 0.0f;
    out[NS * NC * NC + 2 * tid]     = tot;
    out[NS * NC * NC + 2 * tid + 1] = rel;

    __syncthreads();                // everyone done reading accumulators
    g_counts[tid] = 0;              // reset for next graph replay
    if (tid < NC) g_npc[tid] = 0;
}

// ---------------------------------------------------------------------------
extern "C" void kernel_launch(void* const* d_in, const int* in_sizes, int n_in,
                              void* d_out, int out_size) {
    const float* coord = (const float*)d_in[0];   // [S, N, 3] f32
    const int*   asym  = (const int*)  d_in[1];   // [N_TOKENS] i32
    const int*   a2t   = (const int*)  d_in[2];   // [N] i32
    float*       out   = (float*)d_out;

    hist_kernel   <<<(NS * NA) / 256, 256>>>(coord, asym, a2t);
    scan_kernel   <<<NS, 1024>>>();
    scatter_kernel<<<(NS * NA) / 256, 256>>>(coord);
    search_kernel <<<3 * (NS * NA) / 256, 256>>>();
    finalize_kernel<<<1, 256>>>(out);
}

// round 8
// speedup vs baseline: 1.5669x; 1.2065x over previous
#include <cuda_runtime.h>
#include <cuda_bf16.h>

#define NS     4
#define NA     8192
#define NC     8
#define THR2   1.21f
#define GRID   32
#define CELLS  (GRID * GRID * GRID)       // 32768
#define SROW   (CELLS + 4)                // padded row stride (16B multiple)
#define ORIGIN (-22.0f)
#define INV_H  (1.0f / 1.375f)            // cell 1.375 >= 1.1 clash radius

// Device-global scratch (allocation in kernel_launch is forbidden).
// Replay invariants: g_counts, g_npc, g_cellCounts zero on entry (zero-init
// at load; consumers re-zero after reading each replay).
__device__ int g_counts[NS * NC * NC];
__device__ int g_npc[NC];
__device__ __align__(16) int    g_cellCounts[NS][CELLS];
__device__ __align__(16) int    g_cellStarts[NS][SROW];
__device__ int    g_cellrank[NS * NA];    // cell | rank<<15
__device__ int    g_chain[NA];
__device__ __align__(16) float4 g_pk[NS][NA];   // (x,y,z,q) cell-sorted
__device__ int    g_meta[NS][NA];               // chain<<16 | atom id

__device__ __forceinline__ int cellco(float v) {
    int c = __float2int_rd((v - ORIGIN) * INV_H);
    return min(GRID - 1, max(0, c));
}

// ---------------------------------------------------------------------------
// 1) hist: one thread per (sample, atom). The histogram atomic's return value
//    is the atom's rank within its cell -> no second atomic pass needed.
__global__ __launch_bounds__(256) void hist_kernel(
    const float* __restrict__ coord,
    const int*   __restrict__ asym,
    const int*   __restrict__ a2t)
{
    int t = blockIdx.x * 256 + threadIdx.x;   // 0 .. NS*NA-1
    int s = t >> 13;
    float x = coord[3 * t], y = coord[3 * t + 1], z = coord[3 * t + 2];
    int cell = cellco(x) + GRID * (cellco(y) + GRID * cellco(z));
    int rank = atomicAdd(&g_cellCounts[s][cell], 1);
    g_cellrank[t] = cell | (rank << 15);
    if (t < NA) {
        int ch = asym[a2t[t]];
        g_chain[t] = ch;
        atomicAdd(&g_npc[ch], 1);
    }
}

// ---------------------------------------------------------------------------
// 2) scan: one block per sample; warp-shuffle two-level exclusive scan of the
//    32768 cell counts (2 barriers). Writes starts, zeroes counts (invariant).
__global__ __launch_bounds__(1024, 1) void scan_kernel() {
    __shared__ int s_w[32];
    int s    = blockIdx.x;
    int tid  = threadIdx.x;
    int lane = tid & 31;
    int wid  = tid >> 5;

    int base = tid * 32;
    const int4* mine = (const int4*)(g_cellCounts[s] + base);
    int4 v[8];
    int sum = 0;
#pragma unroll
    for (int k = 0; k < 8; ++k) {
        v[k] = mine[k];
        sum += v[k].x + v[k].y + v[k].z + v[k].w;
    }
    // warp-inclusive scan of per-thread sums
    int inc = sum;
#pragma unroll
    for (int d = 1; d < 32; d <<= 1) {
        int u = __shfl_up_sync(0xFFFFFFFF, inc, d);
        if (lane >= d) inc += u;
    }
    if (lane == 31) s_w[wid] = inc;
    __syncthreads();
    if (wid == 0) {
        int t0 = s_w[lane];
        int i2 = t0;
#pragma unroll
        for (int d = 1; d < 32; d <<= 1) {
            int u = __shfl_up_sync(0xFFFFFFFF, i2, d);
            if (lane >= d) i2 += u;
        }
        s_w[lane] = i2 - t0;               // exclusive warp offsets
    }
    __syncthreads();
    int run = s_w[wid] + (inc - sum);      // exclusive start for this thread

    int4* st4 = (int4*)(g_cellStarts[s] + base);
    int4* cc4 = (int4*)(g_cellCounts[s] + base);
#pragma unroll
    for (int k = 0; k < 8; ++k) {
        int4 o;
        o.x = run;           run += v[k].x;
        o.y = run;           run += v[k].y;
        o.z = run;           run += v[k].z;
        o.w = run;           run += v[k].w;
        st4[k] = o;
        cc4[k] = make_int4(0, 0, 0, 0);    // restore replay invariant
    }
    if (tid == 0) g_cellStarts[s][CELLS] = NA;
}

// ---------------------------------------------------------------------------
// 3) scatter: atomic-free; pos = starts[cell] + rank.
__global__ __launch_bounds__(256) void scatter_kernel(
    const float* __restrict__ coord)
{
    int t = blockIdx.x * 256 + threadIdx.x;
    int s = t >> 13;
    int a = t & (NA - 1);
    float x = coord[3 * t], y = coord[3 * t + 1], z = coord[3 * t + 2];
    float q = fmaf(x, x, fmaf(y, y, z * z));
    int cr   = g_cellrank[t];
    int cell = cr & 0x7FFF;
    int rank = cr >> 15;
    int pos  = g_cellStarts[s][cell] + rank;
    g_pk[s][pos]   = make_float4(x, y, z, q);
    g_meta[s][pos] = (g_chain[a] << 16) | a;
}

// ---------------------------------------------------------------------------
// 4) search: one thread per (atom, stencil row) — 9 rows (3z x 3y), each an
//    x-contiguous range of ~3 cells. Pair predicate keeps the exact fp32
//    association of the accepted brute-force kernel; pair counted once
//    (id_j > id_i, cross-chain only).
__global__ __launch_bounds__(256, 8) void search_kernel() {
    __shared__ int scnt[NC * NC];
    int tid = threadIdx.x;
    if (tid < NC * NC) scnt[tid] = 0;
    __syncthreads();

    int b    = blockIdx.x;            // 0 .. 9*128-1
    int roff = b >> 7;                // 0..8: stencil row
    int t    = ((b & 127) << 8) | tid;
    int s    = t >> 13;
    int k    = t & (NA - 1);

    float4 p = g_pk[s][k];
    int    m = g_meta[s][k];
    int    ci   = m >> 16;
    int    myid = m & 0xFFFF;

    float m2x = -2.0f * p.x, m2y = -2.0f * p.y, m2z = -2.0f * p.z;
    float K   = p.w - THR2;

    int cx = cellco(p.x);
    int yy = cellco(p.y) + (roff % 3) - 1;
    int zz = cellco(p.z) + (roff / 3) - 1;
    int x0 = max(cx - 1, 0), x1 = min(cx + 1, GRID - 1);

    if (yy >= 0 && yy < GRID && zz >= 0 && zz < GRID) {
        const float4* pk = g_pk[s];
        const int*    mt = g_meta[s];
        const int*    st = g_cellStarts[s];
        int bucket = ci * NC;

        int row = GRID * (yy + GRID * zz);
        int lo = st[row + x0];
        int hi = st[row + x1 + 1];
        int j = lo;
        for (; j + 1 < hi; j += 2) {
            float4 a = pk[j];
            float4 c = pk[j + 1];
            int ma = mt[j];
            int mb = mt[j + 1];
            float da = fmaf(m2z, a.z, fmaf(m2y, a.y, fmaf(m2x, a.x, a.w))) + K;
            float db = fmaf(m2z, c.z, fmaf(m2y, c.y, fmaf(m2x, c.x, c.w))) + K;
            if (da < 0.0f && (ma & 0xFFFF) > myid && (ma >> 16) != ci)
                atomicAdd(&scnt[bucket + (ma >> 16)], 1);
            if (db < 0.0f && (mb & 0xFFFF) > myid && (mb >> 16) != ci)
                atomicAdd(&scnt[bucket + (mb >> 16)], 1);
        }
        if (j < hi) {
            float4 a = pk[j];
            int ma = mt[j];
            float da = fmaf(m2z, a.z, fmaf(m2y, a.y, fmaf(m2x, a.x, a.w))) + K;
            if (da < 0.0f && (ma & 0xFFFF) > myid && (ma >> 16) != ci)
                atomicAdd(&scnt[bucket + (ma >> 16)], 1);
        }
    }

    __syncthreads();
    if (tid < NC * NC) {
        int v = scnt[tid];
        if (v) atomicAdd(&g_counts[s * NC * NC + tid], v);
    }
}

// ---------------------------------------------------------------------------
// 5) finalize: thresholds + output; resets replay accumulators.
// layout: [ has (S*C*C floats) | details (S*C*C*2 floats, (total, rel)) ]
__global__ void finalize_kernel(float* __restrict__ out) {
    int tid = threadIdx.x;          // 0..255 -> (s, a, b)
    int s = tid >> 6;
    int r = tid & 63;
    int a = r >> 3;
    int b = r & 7;

    int tot_i = 0;
    if (a != b)   // each unordered cross pair counted exactly once total
        tot_i = g_counts[s * NC * NC + a * NC + b] +
                g_counts[s * NC * NC + b * NC + a];
    float tot = (float)tot_i;
    float mn  = (float)min(g_npc[a], g_npc[b]);
    float rel = tot / mn;
    bool  has = (tot > 100.0f) || (rel > 0.5f);

    out[tid]                        = has ? 1.0f : 0.0f;
    out[NS * NC * NC + 2 * tid]     = tot;
    out[NS * NC * NC + 2 * tid + 1] = rel;

    __syncthreads();                // everyone done reading accumulators
    g_counts[tid] = 0;              // reset for next graph replay
    if (tid < NC) g_npc[tid] = 0;
}

// ---------------------------------------------------------------------------
extern "C" void kernel_launch(void* const* d_in, const int* in_sizes, int n_in,
                              void* d_out, int out_size) {
    const float* coord = (const float*)d_in[0];   // [S, N, 3] f32
    const int*   asym  = (const int*)  d_in[1];   // [N_TOKENS] i32
    const int*   a2t   = (const int*)  d_in[2];   // [N] i32
    float*       out   = (float*)d_out;

    hist_kernel    <<<(NS * NA) / 256, 256>>>(coord, asym, a2t);
    scan_kernel    <<<NS, 1024>>>();
    scatter_kernel <<<(NS * NA) / 256, 256>>>(coord);
    search_kernel  <<<9 * (NS * NA) / 256, 256>>>();
    finalize_kernel<<<1, 256>>>(out);
}